// round 1
// baseline (speedup 1.0000x reference)
#include <cuda_runtime.h>

#define NB   32768
#define PP   32
#define NCC  33

// Block partial sums (no device allocation allowed)
__device__ float g_partials[256];

__device__ __forceinline__ float ce_loss(const float* __restrict__ row, int tgt, int* amax_out) {
    // pass 1: max + first-occurrence argmax
    float m = -1e30f; int amax = 0;
#pragma unroll
    for (int j = 0; j < NCC; j++) {
        float x = __ldg(row + j);
        if (x > m) { m = x; amax = j; }
    }
    // pass 2: sum exp(x - m)  (L1 hits)
    float s = 0.f;
#pragma unroll
    for (int j = 0; j < NCC; j++) {
        float x = __ldg(row + j);
        s += __expf(x - m);
    }
    float xt = __ldg(row + tgt);
    *amax_out = amax;
    return m + __logf(s) - xt;   // logsumexp - x_target
}

__device__ __forceinline__ float chamfer(const float4* __restrict__ pred4,
                                         const float4* __restrict__ tgt4,
                                         int np, int nt) {
    // Preload target points into registers; invalid -> far sentinel (+1e18)
    float tvx[PP], tvy[PP];
    float sum_tsq = 0.f;
#pragma unroll
    for (int i = 0; i < PP / 2; i++) {
        float4 v = __ldg(tgt4 + i);
        const int t0 = 2 * i, t1 = 2 * i + 1;
        if (t0 < nt) { sum_tsq += v.x * v.x + v.y * v.y; tvx[t0] = v.x; tvy[t0] = v.y; }
        else         { tvx[t0] = 1e18f; tvy[t0] = 1e18f; }
        if (t1 < nt) { sum_tsq += v.z * v.z + v.w * v.w; tvx[t1] = v.z; tvy[t1] = v.w; }
        else         { tvx[t1] = 1e18f; tvy[t1] = 1e18f; }
    }

    float mint[PP];
#pragma unroll
    for (int t = 0; t < PP; t++) mint[t] = 1e30f;

    float sum_minp = 0.f, sum_psq = 0.f;

    // Outer loop NOT unrolled (I$): 2 pred points per iteration -> 2 independent
    // min chains in flight, 4 fma-pipe + 2 alu-pipe instr per pair.
#pragma unroll 1
    for (int i = 0; i < PP / 2; i++) {
        float4 v = __ldg(pred4 + i);
        const int p0 = 2 * i, p1 = 2 * i + 1;
        float ax = v.x, ay = v.y, bx = v.z, by = v.w;
        const bool va = (p0 < np), vb = (p1 < np);
        if (va) sum_psq += ax * ax + ay * ay; else { ax = -1e18f; ay = -1e18f; }
        if (vb) sum_psq += bx * bx + by * by; else { bx = -1e18f; by = -1e18f; }

        float mina = 1e30f, minb = 1e30f;
#pragma unroll
        for (int t = 0; t < PP; t++) {
            float dax = ax - tvx[t], day = ay - tvy[t];
            float da  = dax * dax + day * day;
            float dbx = bx - tvx[t], dby = by - tvy[t];
            float db  = dbx * dbx + dby * dby;
            mina    = fminf(mina, da);
            minb    = fminf(minb, db);
            mint[t] = fminf(mint[t], fminf(da, db));
        }
        if (va) sum_minp += mina;
        if (vb) sum_minp += minb;
    }

    float sum_mint = 0.f;
#pragma unroll
    for (int t = 0; t < PP; t++)
        if (t < nt) sum_mint += mint[t];

    if (np == 0 && nt == 0) return 0.f;
    if (np == 0) return sum_tsq;
    if (nt == 0) return sum_psq;
    return sum_minp / (float)np + sum_mint / (float)nt;
}

__global__ __launch_bounds__(128)
void loss_kernel(const float*  __restrict__ pole_logits,
                 const float*  __restrict__ zero_logits,
                 const float4* __restrict__ poles,
                 const float4* __restrict__ zeros,
                 const float4* __restrict__ tpoles,
                 const float4* __restrict__ tzeros,
                 const int*    __restrict__ tnp,
                 const int*    __restrict__ tnz) {
    const int b = blockIdx.x * 128 + threadIdx.x;
    float acc = 0.f;
    if (b < NB) {
        const int tp = __ldg(tnp + b);
        const int tz = __ldg(tnz + b);
        int pred_np, pred_nz;
        const float ce_p = ce_loss(pole_logits + (size_t)b * NCC, tp, &pred_np);
        const float ce_z = ce_loss(zero_logits + (size_t)b * NCC, tz, &pred_nz);
        const float ch_p = chamfer(poles + (size_t)b * (PP / 2), tpoles + (size_t)b * (PP / 2), pred_np, tp);
        const float ch_z = chamfer(zeros + (size_t)b * (PP / 2), tzeros + (size_t)b * (PP / 2), pred_nz, tz);
        acc = 5.f * ce_p + 5.f * ce_z + ch_p + ch_z;
    }

    // deterministic block tree reduction
    __shared__ float sred[128];
    sred[threadIdx.x] = acc;
    __syncthreads();
#pragma unroll
    for (int s = 64; s > 0; s >>= 1) {
        if (threadIdx.x < s) sred[threadIdx.x] += sred[threadIdx.x + s];
        __syncthreads();
    }
    if (threadIdx.x == 0) g_partials[blockIdx.x] = sred[0];
}

__global__ void final_reduce(float* __restrict__ out) {
    __shared__ float sred[256];
    sred[threadIdx.x] = g_partials[threadIdx.x];
    __syncthreads();
#pragma unroll
    for (int s = 128; s > 0; s >>= 1) {
        if (threadIdx.x < s) sred[threadIdx.x] += sred[threadIdx.x + s];
        __syncthreads();
    }
    if (threadIdx.x == 0) out[0] = sred[0] * (1.0f / (float)NB);
}

extern "C" void kernel_launch(void* const* d_in, const int* in_sizes, int n_in,
                              void* d_out, int out_size) {
    const float*  pole_logits = (const float*)d_in[0];
    const float*  zero_logits = (const float*)d_in[1];
    const float4* poles       = (const float4*)d_in[2];
    const float4* zeros       = (const float4*)d_in[3];
    const float4* tpoles      = (const float4*)d_in[4];
    const float4* tzeros      = (const float4*)d_in[5];
    const int*    tnp         = (const int*)d_in[6];
    const int*    tnz         = (const int*)d_in[7];

    loss_kernel<<<NB / 128, 128>>>(pole_logits, zero_logits, poles, zeros,
                                   tpoles, tzeros, tnp, tnz);
    final_reduce<<<1, 256>>>((float*)d_out);
}

// round 2
// speedup vs baseline: 1.0570x; 1.0570x over previous
#include <cuda_runtime.h>

#define NB   32768
#define PP   32
#define NCC  33

__device__ float g_partials[256];
__device__ int   g_count;   // zero-init; reset by finishing block each launch

typedef unsigned long long ull;

__device__ __forceinline__ ull ffma2(ull a, ull b, ull c) {
    ull d;
    asm("fma.rn.f32x2 %0, %1, %2, %3;" : "=l"(d) : "l"(a), "l"(b), "l"(c));
    return d;
}
__device__ __forceinline__ ull fadd2(ull a, ull b) {
    ull d;
    asm("add.rn.f32x2 %0, %1, %2;" : "=l"(d) : "l"(a), "l"(b));
    return d;
}
__device__ __forceinline__ ull pack2(float lo, float hi) {
    ull d;
    asm("mov.b64 %0, {%1, %2};" : "=l"(d) : "f"(lo), "f"(hi));
    return d;
}
__device__ __forceinline__ float2 unpack2(ull v) {
    float2 r;
    asm("mov.b64 {%0, %1}, %2;" : "=f"(r.x), "=f"(r.y) : "l"(v));
    return r;
}

// Cross-entropy from a shared-memory row (stride-33 => bank-conflict-free).
__device__ __forceinline__ float ce_smem(const float* __restrict__ row, int tgt, int* amax_out) {
    float m = -1e30f; int amax = 0;
#pragma unroll
    for (int j = 0; j < NCC; j++) {
        float x = row[j];
        if (x > m) { m = x; amax = j; }
    }
    float s = 0.f;
#pragma unroll
    for (int j = 0; j < NCC; j++)
        s += __expf(row[j] - m);
    *amax_out = amax;
    return m + __logf(s) - row[tgt];
}

// Chamfer via |p-t|^2 = |p|^2 + |t|^2 - 2 p.t, packed f32x2 over target pairs.
__device__ __forceinline__ float chamfer(const float4* __restrict__ pred4,
                                         const float4* __restrict__ tgt4,
                                         int np, int nt) {
    // Targets in registers: u=-2tx, v=-2ty, w=|t|^2 ; invalid -> (0,0,1e30)
    ull U2[PP / 2], V2[PP / 2], W2[PP / 2];
    float sum_tsq = 0.f;
#pragma unroll
    for (int j = 0; j < PP / 2; j++) {
        float4 t = __ldg(tgt4 + j);
        float u0, v0, w0, u1, v1, w1;
        if (2 * j < nt)     { w0 = t.x * t.x + t.y * t.y; u0 = -2.f * t.x; v0 = -2.f * t.y; sum_tsq += w0; }
        else                { w0 = 1e30f; u0 = 0.f; v0 = 0.f; }
        if (2 * j + 1 < nt) { w1 = t.z * t.z + t.w * t.w; u1 = -2.f * t.z; v1 = -2.f * t.w; sum_tsq += w1; }
        else                { w1 = 1e30f; u1 = 0.f; v1 = 0.f; }
        U2[j] = pack2(u0, u1); V2[j] = pack2(v0, v1); W2[j] = pack2(w0, w1);
    }

    float mintlo[PP / 2], minthi[PP / 2];
#pragma unroll
    for (int j = 0; j < PP / 2; j++) { mintlo[j] = 1e30f; minthi[j] = 1e30f; }

    float sum_minp = 0.f, sum_psq = 0.f;

#pragma unroll 1
    for (int i = 0; i < PP / 2; i++) {
        float4 p = __ldg(pred4 + i);
        float pna = p.x * p.x + p.y * p.y;
        float pnb = p.z * p.z + p.w * p.w;
        const bool va = (2 * i < np), vb = (2 * i + 1 < np);
        const float pna_d = va ? pna : 1e30f;   // invalid pred never wins mint
        const float pnb_d = vb ? pnb : 1e30f;

        const ull AX = pack2(p.x, p.x), AY = pack2(p.y, p.y);
        const ull BX = pack2(p.z, p.z), BY = pack2(p.w, p.w);
        const ull PA = pack2(pna_d, pna_d), PB = pack2(pnb_d, pnb_d);

        float mina = 1e30f, minb = 1e30f;
#pragma unroll
        for (int j = 0; j < PP / 2; j++) {
            ull ha = ffma2(AY, V2[j], W2[j]); ha = ffma2(AX, U2[j], ha);
            ull hb = ffma2(BY, V2[j], W2[j]); hb = ffma2(BX, U2[j], hb);
            float2 haf = unpack2(ha), hbf = unpack2(hb);
            mina = fminf(mina, fminf(haf.x, haf.y));
            minb = fminf(minb, fminf(hbf.x, hbf.y));
            float2 da = unpack2(fadd2(ha, PA));
            float2 db = unpack2(fadd2(hb, PB));
            mintlo[j] = fminf(mintlo[j], fminf(da.x, db.x));
            minthi[j] = fminf(minthi[j], fminf(da.y, db.y));
        }
        if (va) { sum_minp += mina + pna; sum_psq += pna; }
        if (vb) { sum_minp += minb + pnb; sum_psq += pnb; }
    }

    float sum_mint = 0.f;
#pragma unroll
    for (int j = 0; j < PP / 2; j++) {
        if (2 * j < nt)     sum_mint += mintlo[j];
        if (2 * j + 1 < nt) sum_mint += minthi[j];
    }

    if (np == 0 && nt == 0) return 0.f;
    if (np == 0) return sum_tsq;
    if (nt == 0) return sum_psq;
    return sum_minp / (float)np + sum_mint / (float)nt;
}

__global__ __launch_bounds__(128)
void loss_kernel(const float*  __restrict__ pole_logits,
                 const float*  __restrict__ zero_logits,
                 const float4* __restrict__ poles,
                 const float4* __restrict__ zeros,
                 const float4* __restrict__ tpoles,
                 const float4* __restrict__ tzeros,
                 const int*    __restrict__ tnp,
                 const int*    __restrict__ tnz,
                 float*        __restrict__ out) {
    __shared__ float slog[2][128 * NCC];   // 33792 B
    __shared__ float sred[128];
    __shared__ int   sflag;

    const int tid = threadIdx.x;
    const int b   = blockIdx.x * 128 + tid;

    // Coalesced global -> shared staging of both logit blocks.
    {
        const size_t base = (size_t)blockIdx.x * 128 * NCC;
#pragma unroll 1
        for (int i = tid; i < 128 * NCC; i += 128) {
            slog[0][i] = __ldg(pole_logits + base + i);
            slog[1][i] = __ldg(zero_logits + base + i);
        }
    }
    if (tid == 0) sflag = 0;
    __syncthreads();

    const int tp = __ldg(tnp + b);
    const int tz = __ldg(tnz + b);
    int pred_np, pred_nz;
    const float ce_p = ce_smem(&slog[0][tid * NCC], tp, &pred_np);
    const float ce_z = ce_smem(&slog[1][tid * NCC], tz, &pred_nz);
    const float ch_p = chamfer(poles + (size_t)b * (PP / 4), tpoles + (size_t)b * (PP / 4), pred_np, tp);
    const float ch_z = chamfer(zeros + (size_t)b * (PP / 4), tzeros + (size_t)b * (PP / 4), pred_nz, tz);
    float acc = 5.f * ce_p + 5.f * ce_z + ch_p + ch_z;

    // Deterministic block tree reduction
    sred[tid] = acc;
    __syncthreads();
#pragma unroll
    for (int s = 64; s > 0; s >>= 1) {
        if (tid < s) sred[tid] += sred[tid + s];
        __syncthreads();
    }

    // Last-block final reduction (deterministic: fixed-order tree over g_partials)
    if (tid == 0) {
        g_partials[blockIdx.x] = sred[0];
        __threadfence();
        unsigned n = atomicAdd(&g_count, 1);
        if (n == 255) sflag = 1;
    }
    __syncthreads();

    if (sflag) {
        __threadfence();
        volatile float* vp = g_partials;
        sred[tid] = vp[tid] + vp[tid + 128];
        __syncthreads();
#pragma unroll
        for (int s = 64; s > 0; s >>= 1) {
            if (tid < s) sred[tid] += sred[tid + s];
            __syncthreads();
        }
        if (tid == 0) {
            out[0] = sred[0] * (1.0f / (float)NB);
            g_count = 0;   // reset for next graph replay
        }
    }
}

extern "C" void kernel_launch(void* const* d_in, const int* in_sizes, int n_in,
                              void* d_out, int out_size) {
    const float*  pole_logits = (const float*)d_in[0];
    const float*  zero_logits = (const float*)d_in[1];
    const float4* poles       = (const float4*)d_in[2];
    const float4* zeros       = (const float4*)d_in[3];
    const float4* tpoles      = (const float4*)d_in[4];
    const float4* tzeros      = (const float4*)d_in[5];
    const int*    tnp         = (const int*)d_in[6];
    const int*    tnz         = (const int*)d_in[7];

    loss_kernel<<<NB / 128, 128>>>(pole_logits, zero_logits, poles, zeros,
                                   tpoles, tzeros, tnp, tnz, (float*)d_out);
}

// round 3
// speedup vs baseline: 1.0645x; 1.0072x over previous
#include <cuda_runtime.h>

#define NB   32768
#define PP   32
#define NCC  33
#define NBLK 512   // 2 sides x 256 item-blocks

__device__ float g_partials[NBLK];
__device__ int   g_count;   // zero-init; reset by finishing block each launch

typedef unsigned long long ull;

__device__ __forceinline__ ull ffma2(ull a, ull b, ull c) {
    ull d; asm("fma.rn.f32x2 %0, %1, %2, %3;" : "=l"(d) : "l"(a), "l"(b), "l"(c)); return d;
}
__device__ __forceinline__ ull fadd2(ull a, ull b) {
    ull d; asm("add.rn.f32x2 %0, %1, %2;" : "=l"(d) : "l"(a), "l"(b)); return d;
}
__device__ __forceinline__ ull fmul2(ull a, ull b) {
    ull d; asm("mul.rn.f32x2 %0, %1, %2;" : "=l"(d) : "l"(a), "l"(b)); return d;
}
__device__ __forceinline__ ull pack2(float lo, float hi) {
    ull d; asm("mov.b64 %0, {%1, %2};" : "=l"(d) : "f"(lo), "f"(hi)); return d;
}
__device__ __forceinline__ float2 unpack2(ull v) {
    float2 r; asm("mov.b64 {%0, %1}, %2;" : "=f"(r.x), "=f"(r.y) : "l"(v)); return r;
}

// Cross-entropy from a shared-memory row (stride-33 => conflict-free).
__device__ __forceinline__ float ce_smem(const float* __restrict__ row, int tgt, int* amax_out) {
    float m = -1e30f; int amax = 0;
#pragma unroll
    for (int j = 0; j < NCC; j++) {
        float x = row[j];
        if (x > m) { m = x; amax = j; }
    }
    float s = 0.f;
#pragma unroll
    for (int j = 0; j < NCC; j++)
        s += __expf(row[j] - m);
    *amax_out = amax;
    return m + __logf(s) - row[tgt];
}

// Chamfer with DIRECT squared differences (accuracy-safe), two targets packed
// per f32x2 register, two pred points per outer iteration.
__device__ __forceinline__ float chamfer(const float4* __restrict__ pred4,
                                         const float4* __restrict__ tgt4,
                                         int np, int nt) {
    // Store NEGATED target coords packed; invalid target -> coord +1e18 (store -1e18).
    ull TX[PP / 2], TY[PP / 2];
    float sum_tsq = 0.f;
#pragma unroll
    for (int j = 0; j < PP / 2; j++) {
        float4 t = __ldg(tgt4 + j);
        float x0, y0, x1, y1;
        if (2 * j < nt)     { sum_tsq += t.x * t.x + t.y * t.y; x0 = -t.x; y0 = -t.y; }
        else                { x0 = -1e18f; y0 = -1e18f; }
        if (2 * j + 1 < nt) { sum_tsq += t.z * t.z + t.w * t.w; x1 = -t.z; y1 = -t.w; }
        else                { x1 = -1e18f; y1 = -1e18f; }
        TX[j] = pack2(x0, x1); TY[j] = pack2(y0, y1);
    }

    float mintlo[PP / 2], minthi[PP / 2];
#pragma unroll
    for (int j = 0; j < PP / 2; j++) { mintlo[j] = 1e30f; minthi[j] = 1e30f; }

    float sum_minp = 0.f, sum_psq = 0.f;

#pragma unroll 1
    for (int i = 0; i < PP / 2; i++) {
        float4 p = __ldg(pred4 + i);
        const bool va = (2 * i < np), vb = (2 * i + 1 < np);
        float ax = p.x, ay = p.y, bx = p.z, by = p.w;
        if (va) sum_psq += ax * ax + ay * ay; else { ax = -1e18f; ay = -1e18f; }
        if (vb) sum_psq += bx * bx + by * by; else { bx = -1e18f; by = -1e18f; }

        const ull AX = pack2(ax, ax), AY = pack2(ay, ay);
        const ull BX = pack2(bx, bx), BY = pack2(by, by);

        float mina = 1e30f, minb = 1e30f;
#pragma unroll
        for (int j = 0; j < PP / 2; j++) {
            ull dxa = fadd2(AX, TX[j]);
            ull dya = fadd2(AY, TY[j]);
            ull da  = ffma2(dxa, dxa, fmul2(dya, dya));
            ull dxb = fadd2(BX, TX[j]);
            ull dyb = fadd2(BY, TY[j]);
            ull db  = ffma2(dxb, dxb, fmul2(dyb, dyb));
            float2 daf = unpack2(da), dbf = unpack2(db);
            mina = fminf(mina, fminf(daf.x, daf.y));
            minb = fminf(minb, fminf(dbf.x, dbf.y));
            mintlo[j] = fminf(mintlo[j], fminf(daf.x, dbf.x));
            minthi[j] = fminf(minthi[j], fminf(daf.y, dbf.y));
        }
        if (va) sum_minp += mina;
        if (vb) sum_minp += minb;
    }

    float sum_mint = 0.f;
#pragma unroll
    for (int j = 0; j < PP / 2; j++) {
        if (2 * j < nt)     sum_mint += mintlo[j];
        if (2 * j + 1 < nt) sum_mint += minthi[j];
    }

    if (np == 0 && nt == 0) return 0.f;
    if (np == 0) return sum_tsq;
    if (nt == 0) return sum_psq;
    return sum_minp / (float)np + sum_mint / (float)nt;
}

// Each block handles 128 items on ONE side (poles or zeros):
//   side = blockIdx.x & 1, item-block = blockIdx.x >> 1.
__global__ __launch_bounds__(128)
void loss_kernel(const float*  __restrict__ pole_logits,
                 const float*  __restrict__ zero_logits,
                 const float4* __restrict__ poles,
                 const float4* __restrict__ zeros,
                 const float4* __restrict__ tpoles,
                 const float4* __restrict__ tzeros,
                 const int*    __restrict__ tnp,
                 const int*    __restrict__ tnz,
                 float*        __restrict__ out) {
    __shared__ float slog[128 * NCC];   // 16896 B
    __shared__ float sred[128];
    __shared__ int   sflag;

    const int tid  = threadIdx.x;
    const int side = blockIdx.x & 1;
    const int ib   = blockIdx.x >> 1;
    const int b    = ib * 128 + tid;

    const float*  logits = side ? zero_logits : pole_logits;
    const float4* pred   = side ? zeros       : poles;
    const float4* tgt    = side ? tzeros      : tpoles;
    const int*    tn     = side ? tnz         : tnp;

    // Coalesced global -> shared staging of this side's logit block.
    {
        const size_t base = (size_t)ib * 128 * NCC;
#pragma unroll 1
        for (int i = tid; i < 128 * NCC; i += 128)
            slog[i] = __ldg(logits + base + i);
    }
    if (tid == 0) sflag = 0;
    __syncthreads();

    const int tc = __ldg(tn + b);
    int pred_n;
    const float ce = ce_smem(&slog[tid * NCC], tc, &pred_n);
    const float ch = chamfer(pred + (size_t)b * (PP / 2), tgt + (size_t)b * (PP / 2), pred_n, tc);
    float acc = 5.f * ce + ch;

    // Deterministic block tree reduction
    sred[tid] = acc;
    __syncthreads();
#pragma unroll
    for (int s = 64; s > 0; s >>= 1) {
        if (tid < s) sred[tid] += sred[tid + s];
        __syncthreads();
    }

    if (tid == 0) {
        g_partials[blockIdx.x] = sred[0];
        __threadfence();
        unsigned n = atomicAdd(&g_count, 1);
        if (n == NBLK - 1) sflag = 1;
    }
    __syncthreads();

    // Last block: deterministic fixed-order tree over all partials.
    if (sflag) {
        __threadfence();
        volatile float* vp = g_partials;
        sred[tid] = (vp[tid] + vp[tid + 128]) + (vp[tid + 256] + vp[tid + 384]);
        __syncthreads();
#pragma unroll
        for (int s = 64; s > 0; s >>= 1) {
            if (tid < s) sred[tid] += sred[tid + s];
            __syncthreads();
        }
        if (tid == 0) {
            out[0] = sred[0] * (1.0f / (float)NB);
            g_count = 0;   // reset for next graph replay
        }
    }
}

extern "C" void kernel_launch(void* const* d_in, const int* in_sizes, int n_in,
                              void* d_out, int out_size) {
    const float*  pole_logits = (const float*)d_in[0];
    const float*  zero_logits = (const float*)d_in[1];
    const float4* poles       = (const float4*)d_in[2];
    const float4* zeros       = (const float4*)d_in[3];
    const float4* tpoles      = (const float4*)d_in[4];
    const float4* tzeros      = (const float4*)d_in[5];
    const int*    tnp         = (const int*)d_in[6];
    const int*    tnz         = (const int*)d_in[7];

    loss_kernel<<<NBLK, 128>>>(pole_logits, zero_logits, poles, zeros,
                               tpoles, tzeros, tnp, tnz, (float*)d_out);
}

// round 4
// speedup vs baseline: 1.2533x; 1.1773x over previous
#include <cuda_runtime.h>

#define NB   32768
#define PP   32
#define NCC  33
#define NBLK 512   // 2 sides x 256 item-blocks

__device__ float g_partials[NBLK];
__device__ int   g_count;   // zero-init; reset by finishing block each launch

typedef unsigned long long ull;

__device__ __forceinline__ ull ffma2(ull a, ull b, ull c) {
    ull d; asm("fma.rn.f32x2 %0, %1, %2, %3;" : "=l"(d) : "l"(a), "l"(b), "l"(c)); return d;
}
__device__ __forceinline__ ull fadd2(ull a, ull b) {
    ull d; asm("add.rn.f32x2 %0, %1, %2;" : "=l"(d) : "l"(a), "l"(b)); return d;
}
__device__ __forceinline__ ull fmul2(ull a, ull b) {
    ull d; asm("mul.rn.f32x2 %0, %1, %2;" : "=l"(d) : "l"(a), "l"(b)); return d;
}
__device__ __forceinline__ ull pack2(float lo, float hi) {
    ull d; asm("mov.b64 %0, {%1, %2};" : "=l"(d) : "f"(lo), "f"(hi)); return d;
}
__device__ __forceinline__ float2 unpack2(ull v) {
    float2 r; asm("mov.b64 {%0, %1}, %2;" : "=f"(r.x), "=f"(r.y) : "l"(v)); return r;
}

// Cross-entropy from a shared-memory row (stride-33 => conflict-free).
__device__ __forceinline__ float ce_smem(const float* __restrict__ row, int tgt, int* amax_out) {
    float m = -1e30f; int amax = 0;
#pragma unroll
    for (int j = 0; j < NCC; j++) {
        float x = row[j];
        if (x > m) { m = x; amax = j; }
    }
    float s = 0.f;
#pragma unroll
    for (int j = 0; j < NCC; j++)
        s += __expf(row[j] - m);
    *amax_out = amax;
    return m + __logf(s) - row[tgt];
}

// Chamfer with DIRECT squared differences (accuracy-safe), two targets packed
// per f32x2 register, two pred points per unrolled step. Pred loads are
// software-pipelined in chunks of 4 float4 so the LDG latency is hidden
// behind the previous chunk's ~900 compute instructions.
__device__ __forceinline__ float chamfer(const float4* __restrict__ pred4,
                                         const float4* __restrict__ tgt4,
                                         int np, int nt) {
    // Targets (negated, packed); invalid -> -(+1e18). Fully unrolled: 16
    // batched LDG.128 (MLP=16), a single latency exposure.
    ull TX[PP / 2], TY[PP / 2];
    float sum_tsq = 0.f;
#pragma unroll
    for (int j = 0; j < PP / 2; j++) {
        float4 t = __ldg(tgt4 + j);
        float x0, y0, x1, y1;
        if (2 * j < nt)     { sum_tsq += t.x * t.x + t.y * t.y; x0 = -t.x; y0 = -t.y; }
        else                { x0 = -1e18f; y0 = -1e18f; }
        if (2 * j + 1 < nt) { sum_tsq += t.z * t.z + t.w * t.w; x1 = -t.z; y1 = -t.w; }
        else                { x1 = -1e18f; y1 = -1e18f; }
        TX[j] = pack2(x0, x1); TY[j] = pack2(y0, y1);
    }

    float mintlo[PP / 2], minthi[PP / 2];
#pragma unroll
    for (int j = 0; j < PP / 2; j++) { mintlo[j] = 1e30f; minthi[j] = 1e30f; }

    float sum_minp = 0.f, sum_psq = 0.f;

    // Prefetch chunk 0 (4 float4 = 8 pred points), MLP=4.
    float4 buf0 = __ldg(pred4 + 0);
    float4 buf1 = __ldg(pred4 + 1);
    float4 buf2 = __ldg(pred4 + 2);
    float4 buf3 = __ldg(pred4 + 3);

#pragma unroll 1
    for (int c = 0; c < 4; c++) {
        float4 cur0 = buf0, cur1 = buf1, cur2 = buf2, cur3 = buf3;
        if (c < 3) {
            buf0 = __ldg(pred4 + 4 * (c + 1) + 0);
            buf1 = __ldg(pred4 + 4 * (c + 1) + 1);
            buf2 = __ldg(pred4 + 4 * (c + 1) + 2);
            buf3 = __ldg(pred4 + 4 * (c + 1) + 3);
        }
        float4 curs[4] = {cur0, cur1, cur2, cur3};
#pragma unroll
        for (int u = 0; u < 4; u++) {
            const int i = 4 * c + u;
            float4 p = curs[u];
            const bool va = (2 * i < np), vb = (2 * i + 1 < np);
            float ax = p.x, ay = p.y, bx = p.z, by = p.w;
            if (va) sum_psq += ax * ax + ay * ay; else { ax = -1e18f; ay = -1e18f; }
            if (vb) sum_psq += bx * bx + by * by; else { bx = -1e18f; by = -1e18f; }

            const ull AX = pack2(ax, ax), AY = pack2(ay, ay);
            const ull BX = pack2(bx, bx), BY = pack2(by, by);

            float mina = 1e30f, minb = 1e30f;
#pragma unroll
            for (int j = 0; j < PP / 2; j++) {
                ull dxa = fadd2(AX, TX[j]);
                ull dya = fadd2(AY, TY[j]);
                ull da  = ffma2(dxa, dxa, fmul2(dya, dya));
                ull dxb = fadd2(BX, TX[j]);
                ull dyb = fadd2(BY, TY[j]);
                ull db  = ffma2(dxb, dxb, fmul2(dyb, dyb));
                float2 daf = unpack2(da), dbf = unpack2(db);
                mina = fminf(mina, fminf(daf.x, daf.y));
                minb = fminf(minb, fminf(dbf.x, dbf.y));
                mintlo[j] = fminf(mintlo[j], fminf(daf.x, dbf.x));
                minthi[j] = fminf(minthi[j], fminf(daf.y, dbf.y));
            }
            if (va) sum_minp += mina;
            if (vb) sum_minp += minb;
        }
    }

    float sum_mint = 0.f;
#pragma unroll
    for (int j = 0; j < PP / 2; j++) {
        if (2 * j < nt)     sum_mint += mintlo[j];
        if (2 * j + 1 < nt) sum_mint += minthi[j];
    }

    if (np == 0 && nt == 0) return 0.f;
    if (np == 0) return sum_tsq;
    if (nt == 0) return sum_psq;
    return sum_minp / (float)np + sum_mint / (float)nt;
}

// Each block handles 128 items on ONE side (poles or zeros):
//   side = blockIdx.x & 1, item-block = blockIdx.x >> 1.
__global__ __launch_bounds__(128)
void loss_kernel(const float*  __restrict__ pole_logits,
                 const float*  __restrict__ zero_logits,
                 const float4* __restrict__ poles,
                 const float4* __restrict__ zeros,
                 const float4* __restrict__ tpoles,
                 const float4* __restrict__ tzeros,
                 const int*    __restrict__ tnp,
                 const int*    __restrict__ tnz,
                 float*        __restrict__ out) {
    __shared__ __align__(16) float slog[128 * NCC];   // 16896 B
    __shared__ float sred[128];
    __shared__ int   sflag;

    const int tid  = threadIdx.x;
    const int side = blockIdx.x & 1;
    const int ib   = blockIdx.x >> 1;
    const int b    = ib * 128 + tid;

    const float*  logits = side ? zero_logits : pole_logits;
    const float4* pred   = side ? zeros       : poles;
    const float4* tgt    = side ? tzeros      : tpoles;
    const int*    tn     = side ? tnz         : tnp;

    // Coalesced float4 staging, fully unrolled => MLP ~ 9.
    // Block base offset = ib * 128*33 floats = ib * 16896 bytes (16B aligned).
    {
        const float4* src = (const float4*)(logits + (size_t)ib * 128 * NCC);
        float4* dst = (float4*)slog;
#pragma unroll
        for (int k = 0; k < 8; k++)
            dst[tid + 128 * k] = __ldg(src + tid + 128 * k);
        if (tid < 32)
            dst[1024 + tid] = __ldg(src + 1024 + tid);
    }
    if (tid == 0) sflag = 0;
    __syncthreads();

    const int tc = __ldg(tn + b);
    int pred_n;
    const float ce = ce_smem(&slog[tid * NCC], tc, &pred_n);
    const float ch = chamfer(pred + (size_t)b * (PP / 2), tgt + (size_t)b * (PP / 2), pred_n, tc);
    float acc = 5.f * ce + ch;

    // Deterministic block tree reduction
    sred[tid] = acc;
    __syncthreads();
#pragma unroll
    for (int s = 64; s > 0; s >>= 1) {
        if (tid < s) sred[tid] += sred[tid + s];
        __syncthreads();
    }

    if (tid == 0) {
        g_partials[blockIdx.x] = sred[0];
        __threadfence();
        unsigned n = atomicAdd(&g_count, 1);
        if (n == NBLK - 1) sflag = 1;
    }
    __syncthreads();

    // Last block: deterministic fixed-order tree over all partials.
    if (sflag) {
        __threadfence();
        volatile float* vp = g_partials;
        sred[tid] = (vp[tid] + vp[tid + 128]) + (vp[tid + 256] + vp[tid + 384]);
        __syncthreads();
#pragma unroll
        for (int s = 64; s > 0; s >>= 1) {
            if (tid < s) sred[tid] += sred[tid + s];
            __syncthreads();
        }
        if (tid == 0) {
            out[0] = sred[0] * (1.0f / (float)NB);
            g_count = 0;   // reset for next graph replay
        }
    }
}

extern "C" void kernel_launch(void* const* d_in, const int* in_sizes, int n_in,
                              void* d_out, int out_size) {
    const float*  pole_logits = (const float*)d_in[0];
    const float*  zero_logits = (const float*)d_in[1];
    const float4* poles       = (const float4*)d_in[2];
    const float4* zeros       = (const float4*)d_in[3];
    const float4* tpoles      = (const float4*)d_in[4];
    const float4* tzeros      = (const float4*)d_in[5];
    const int*    tnp         = (const int*)d_in[6];
    const int*    tnz         = (const int*)d_in[7];

    loss_kernel<<<NBLK, 128>>>(pole_logits, zero_logits, poles, zeros,
                               tpoles, tzeros, tnp, tnz, (float*)d_out);
}